// round 12
// baseline (speedup 1.0000x reference)
#include <cuda_runtime.h>
#include <cuda_bf16.h>
#include <cstdint>

#define NN 50000
#define NE 200000
#define H  128
#define HV4 32   // H/4

// Scratch (device globals: allocation-free per harness rules)
__device__ float g_node_h[NN * H];        // 25.6 MB  node_h buffer A
__device__ float g_node_h2[NN * H];       // 25.6 MB  node_h buffer B (ping-pong)
__device__ float g_agg_base[NN * H];      // 25.6 MB  Σ edge_h per dst (factorized)
__device__ float g_escratch[NN * 65];     // precompute: eaggF [NN,64] + deg [NN]; layers: sdot_a|sdot_b
__device__ float g_edot[NE];              // folded edge-constant gate logit
__device__ float g_wcombo[65];            // W_edge @ w_top_e (64) + folded bias
// CSR (dst-sorted edge list), built once per call
__device__ int   g_cnt[NN];
__device__ int   g_off[NN + 1];
__device__ int   g_cur[NN];
__device__ int   g_src_csr[NE];
__device__ int   g_eid_csr[NE];
__device__ float g_edot_csr[NE];

__device__ __forceinline__ void fma4(float4& acc, const float4& wv, float s) {
    acc.x += wv.x * s;
    acc.y += wv.y * s;
    acc.z += wv.z * s;
    acc.w += wv.w * s;
}
__device__ __forceinline__ void red_v2(float* p, float a, float b) {
    asm volatile("red.global.add.v2.f32 [%0], {%1,%2};"
                 :: "l"(p), "f"(a), "f"(b) : "memory");
}
__device__ __forceinline__ uint32_t bf16pack(float a, float b) {
    uint32_t r;
    asm("{.reg .b16 x, y; cvt.rn.bf16.f32 x, %1; cvt.rn.bf16.f32 y, %2; mov.b32 %0, {x, y};}"
        : "=r"(r) : "f"(a), "f"(b));
    return r;
}
__device__ __forceinline__ float bf16rn(float x) {
    return __bfloat162float(__float2bfloat16_rn(x));
}
__device__ __forceinline__ void mma16816(float* c,
                                         uint32_t a0, uint32_t a1, uint32_t a2, uint32_t a3,
                                         uint32_t b0, uint32_t b1) {
    asm("mma.sync.aligned.m16n8k16.row.col.f32.bf16.bf16.f32 "
        "{%0,%1,%2,%3}, {%4,%5,%6,%7}, {%8,%9}, {%0,%1,%2,%3};"
        : "+f"(c[0]), "+f"(c[1]), "+f"(c[2]), "+f"(c[3])
        : "r"(a0), "r"(a1), "r"(a2), "r"(a3), "r"(b0), "r"(b1));
}

__global__ void zero_kernel(float4* __restrict__ p, int n4) {
    int i = blockIdx.x * blockDim.x + threadIdx.x;
    if (i < n4) p[i] = make_float4(0.f, 0.f, 0.f, 0.f);
}

// ---------------------------------------------------------------------------
__global__ void combo_kernel(const float* __restrict__ W_edge,
                             const float* __restrict__ W_top,
                             const float* __restrict__ b_edge,
                             const float* __restrict__ b_top,
                             float* __restrict__ wcombo)
{
    const int k = threadIdx.x;   // 64 threads
    float s = 0.f;
    for (int h = 0; h < H; h++) s += W_edge[k * H + h] * W_top[2 * H + h];
    wcombo[k] = s;
    if (k == 0) {
        float b = b_top[0];
        for (int h = 0; h < H; h++) b += b_edge[h] * W_top[2 * H + h];
        wcombo[64] = b;
    }
}

// ---------------------------------------------------------------------------
__global__ void edge_pre_kernel(const float* __restrict__ ef,
                                const int* __restrict__ dst,
                                const float* __restrict__ wcombo,
                                float* __restrict__ eaggF,
                                float* __restrict__ deg,
                                int* __restrict__ cnt,
                                float* __restrict__ edot)
{
    __shared__ float wsh[65];
    const int tid  = threadIdx.x;
    const int lane = tid & 31;
    const int wid  = tid >> 5;
    if (tid < 65) wsh[tid] = wcombo[tid];
    __syncthreads();

    const int e = blockIdx.x * 8 + wid;
    const int d = dst[e];
    float2 v = ((const float2*)ef)[(size_t)e * 32 + lane];
    float p = v.x * wsh[lane * 2] + v.y * wsh[lane * 2 + 1];
    #pragma unroll
    for (int off = 16; off; off >>= 1)
        p += __shfl_xor_sync(0xffffffffu, p, off);
    if (lane == 0) {
        edot[e] = p + wsh[64];
        atomicAdd(deg + d, 1.f);
        atomicAdd(cnt + d, 1);
    }
    red_v2(eaggF + (size_t)d * 64 + lane * 2, v.x, v.y);
}

// ---------------------------------------------------------------------------
__global__ void scan_kernel(const int* __restrict__ cnt,
                            int* __restrict__ off,
                            int* __restrict__ cur)
{
    __shared__ int sums[1024];
    const int t = threadIdx.x;
    const int CH = (NN + 1023) / 1024;   // 49
    const int base = t * CH;
    int s = 0;
    for (int i = 0; i < CH; i++) {
        const int idx = base + i;
        if (idx < NN) s += cnt[idx];
    }
    sums[t] = s;
    __syncthreads();
    int x = s;
    for (int d = 1; d < 1024; d <<= 1) {
        const int y = (t >= d) ? sums[t - d] : 0;
        __syncthreads();
        x += y;
        sums[t] = x;
        __syncthreads();
    }
    int run = x - s;   // exclusive prefix
    for (int i = 0; i < CH; i++) {
        const int idx = base + i;
        if (idx < NN) {
            off[idx] = run;
            cur[idx] = run;
            run += cnt[idx];
        }
    }
    if (t == 1023) off[NN] = NE;
}

__global__ void scatter_kernel(const int* __restrict__ src,
                               const int* __restrict__ dst,
                               const float* __restrict__ edot,
                               int* __restrict__ cur,
                               int* __restrict__ src_csr,
                               int* __restrict__ eid_csr,
                               float* __restrict__ edot_csr)
{
    const int e = blockIdx.x * 256 + threadIdx.x;
    if (e >= NE) return;
    const int d = dst[e];
    const int pos = atomicAdd(cur + d, 1);
    src_csr[pos]  = src[e];
    eid_csr[pos]  = e;
    edot_csr[pos] = edot[e];
}

// ---------------------------------------------------------------------------
// Embed GEMM (R3-proven): out[rows,H] = X[rows,K] @ W[K,H] + scale*b
// ---------------------------------------------------------------------------
template<int K, bool DEGBIAS, bool SDOT>
__global__ void embed_kernel(const float* __restrict__ X,
                             const float* __restrict__ W,
                             const float* __restrict__ b,
                             const float* __restrict__ deg,
                             const float* __restrict__ W_top,
                             float* __restrict__ out,
                             float2* __restrict__ sdot2, int rows)
{
    extern __shared__ float sm[];
    float* Wsh  = sm;            // K*H floats
    float* xbuf = sm + K * H;    // 32*K floats

    const int tid  = threadIdx.x;
    const int lane = tid & 31;
    const int wid  = tid >> 5;

    for (int i = tid; i < K * H / 4; i += 256)
        ((float4*)Wsh)[i] = ((const float4*)W)[i];
    const float4 bias = ((const float4*)b)[lane];
    float4 wsA, wdA;
    if (SDOT) {
        wsA = ((const float4*)W_top)[lane];
        wdA = ((const float4*)W_top)[32 + lane];
    }

    for (int r0 = blockIdx.x * 32; r0 < rows; r0 += gridDim.x * 32) {
        __syncthreads();
        const int nrows = min(32, rows - r0);
        for (int i = tid; i < nrows * (K / 4); i += 256)
            ((float4*)xbuf)[i] = ((const float4*)(X + (size_t)r0 * K))[i];
        __syncthreads();

        const int rbase = wid * 4;
        if (rbase < nrows) {
            float4 acc0 = make_float4(0.f, 0.f, 0.f, 0.f);
            float4 acc1 = acc0, acc2 = acc0, acc3 = acc0;
            const float* xr0 = xbuf + (rbase + 0) * K;
            const float* xr1 = xbuf + (rbase + 1) * K;
            const float* xr2 = xbuf + (rbase + 2) * K;
            const float* xr3 = xbuf + (rbase + 3) * K;
            #pragma unroll 4
            for (int k = 0; k < K; k++) {
                float4 wv = ((float4*)Wsh)[k * HV4 + lane];
                fma4(acc0, wv, xr0[k]);
                fma4(acc1, wv, xr1[k]);
                fma4(acc2, wv, xr2[k]);
                fma4(acc3, wv, xr3[k]);
            }
            float4 accs[4] = {acc0, acc1, acc2, acc3};
            #pragma unroll
            for (int rr = 0; rr < 4; rr++) {
                const float scb = DEGBIAS ? deg[r0 + rbase + rr] : 1.f;
                float4 o;
                o.x = accs[rr].x + scb * bias.x;
                o.y = accs[rr].y + scb * bias.y;
                o.z = accs[rr].z + scb * bias.z;
                o.w = accs[rr].w + scb * bias.w;
                ((float4*)out)[(size_t)(r0 + rbase + rr) * HV4 + lane] = o;
                if (SDOT) {
                    float s1 = o.x * wsA.x + o.y * wsA.y + o.z * wsA.z + o.w * wsA.w;
                    float s2 = o.x * wdA.x + o.y * wdA.y + o.z * wdA.z + o.w * wdA.w;
                    #pragma unroll
                    for (int off = 16; off; off >>= 1) {
                        s1 += __shfl_xor_sync(0xffffffffu, s1, off);
                        s2 += __shfl_xor_sync(0xffffffffu, s2, off);
                    }
                    if (lane == 0) sdot2[r0 + rbase + rr] = make_float2(s1, s2);
                }
            }
        }
    }
}

// ---------------------------------------------------------------------------
// Fused GNN layer: CSR aggregation + bf16-split TC GEMM + LN/ReLU.
// 1024 threads (32 warps). Aggregation: warp owns 2 nodes. MMA warp tile:
// 16 rows x 16 cols (2 n-tiles). LN combine across 8 column partials.
// ---------------------------------------------------------------------------
#define A_STR 73
#define B_STR 136
#define A_PLANE (128 * A_STR)
#define B_PLANE (128 * B_STR)
#define SMEM_TC ((2 * A_PLANE + 2 * B_PLANE + 640 + 1024 + 1024) * 4)

template<bool LAST>
__global__ void __launch_bounds__(1024, 1)
gnn_fused_kernel(const float* __restrict__ nh_old,
                 float* __restrict__ nh_new,
                 const float* __restrict__ agg_base,
                 const int* __restrict__ off,
                 const int* __restrict__ src_csr,
                 const int* __restrict__ eid_csr,
                 const float* __restrict__ edot_csr,
                 const float2* __restrict__ sdot_cur,
                 float2* __restrict__ sdot_nxt,
                 const float* __restrict__ W,      // [256,128]
                 const float* __restrict__ b,
                 const float* __restrict__ lns,
                 const float* __restrict__ lnb,
                 const float* __restrict__ W_top,
                 float* __restrict__ ew, int rows)
{
    extern __shared__ uint32_t smu[];
    uint32_t* Ahi = smu;
    uint32_t* Alo = Ahi + A_PLANE;
    uint32_t* Bhi = Alo + A_PLANE;
    uint32_t* Blo = Bhi + B_PLANE;
    float*    prm = (float*)(Blo + B_PLANE);        // 640 floats: b|lns|lnb|ws|wd
    float2*   red = (float2*)(prm + 640);           // [64 rows][8 col-partials]
    float2*   sdp = red + 512;                      // [64 rows][8 col-partials]

    const int tid  = threadIdx.x;
    const int lane = tid & 31;
    const int w    = tid >> 5;
    const int t4   = lane & 3;
    const int g    = lane >> 2;

    const float2* nh2   = (const float2*)nh_old;
    float2*       outp2 = (float2*)nh_new;
    const float2* prm2  = (const float2*)prm;

    // ---- stage W (once): packed bf16x2 hi/lo planes ----
    for (int i = tid; i < 128 * 128; i += 1024) {
        const int kp = i >> 7, n = i & 127;
        const float w0 = W[(size_t)(2 * kp) * 128 + n];
        const float w1 = W[(size_t)(2 * kp + 1) * 128 + n];
        const float h0 = bf16rn(w0);
        const float h1 = bf16rn(w1);
        Bhi[kp * B_STR + n] = bf16pack(h0, h1);
        Blo[kp * B_STR + n] = bf16pack(w0 - h0, w1 - h1);
    }
    for (int i = tid; i < 128; i += 1024) {
        prm[i]       = b[i];
        prm[128 + i] = lns[i];
        prm[256 + i] = lnb[i];
        prm[384 + i] = W_top[i];
        prm[512 + i] = W_top[128 + i];
    }

    const int roffL = (w >> 3) * 16;     // row group: 0/16/32/48
    const int cgrp  = w & 7;             // col group 0..7
    const int noff  = cgrp * 16;         // 16 cols per warp

    for (int r0 = blockIdx.x * 64; r0 < rows; r0 += gridDim.x * 64) {
        __syncthreads();
        const int nrows = min(64, rows - r0);

        // ---- stage + aggregate: warp owns nodes w*2, w*2+1 ----
        for (int q = 0; q < 2; q++) {
            const int rl = w * 2 + q;
            float4 nh4 = make_float4(0.f, 0.f, 0.f, 0.f);
            float4 acc = make_float4(0.f, 0.f, 0.f, 0.f);
            if (rl < nrows) {
                const int node = r0 + rl;
                nh4 = ((const float4*)nh_old)[(size_t)node * HV4 + lane];
                acc = ((const float4*)agg_base)[(size_t)node * HV4 + lane];
                const float sdy = sdot_cur[node].y;
                const int beg = off[node], end = off[node + 1];
                for (int jb = beg; jb < end; jb += 32) {
                    const int j = jb + lane;
                    float wgt = 0.f;
                    int   sj  = 0;
                    if (j < end) {
                        sj = src_csr[j];
                        const float p = sdot_cur[sj].x + sdy + edot_csr[j];
                        wgt = 1.f / (1.f + __expf(-p));
                        if (LAST) ew[eid_csr[j]] = wgt;
                    }
                    const int m = min(32, end - jb);
                    float4 a1 = make_float4(0.f, 0.f, 0.f, 0.f);
                    float4 a2 = a1, a3 = a1;
                    int jj = 0;
                    for (; jj + 4 <= m; jj += 4) {
                        const int s0 = __shfl_sync(0xffffffffu, sj, jj);
                        const int s1 = __shfl_sync(0xffffffffu, sj, jj + 1);
                        const int s2 = __shfl_sync(0xffffffffu, sj, jj + 2);
                        const int s3 = __shfl_sync(0xffffffffu, sj, jj + 3);
                        const float w0 = __shfl_sync(0xffffffffu, wgt, jj);
                        const float w1 = __shfl_sync(0xffffffffu, wgt, jj + 1);
                        const float w2 = __shfl_sync(0xffffffffu, wgt, jj + 2);
                        const float w3 = __shfl_sync(0xffffffffu, wgt, jj + 3);
                        const float4 f0 = ((const float4*)nh_old)[(size_t)s0 * HV4 + lane];
                        const float4 f1 = ((const float4*)nh_old)[(size_t)s1 * HV4 + lane];
                        const float4 f2 = ((const float4*)nh_old)[(size_t)s2 * HV4 + lane];
                        const float4 f3 = ((const float4*)nh_old)[(size_t)s3 * HV4 + lane];
                        fma4(acc, f0, w0);
                        fma4(a1, f1, w1);
                        fma4(a2, f2, w2);
                        fma4(a3, f3, w3);
                    }
                    for (; jj < m; jj++) {
                        const int s0 = __shfl_sync(0xffffffffu, sj, jj);
                        const float w0 = __shfl_sync(0xffffffffu, wgt, jj);
                        const float4 f0 = ((const float4*)nh_old)[(size_t)s0 * HV4 + lane];
                        fma4(acc, f0, w0);
                    }
                    acc.x += a1.x + a2.x + a3.x;
                    acc.y += a1.y + a2.y + a3.y;
                    acc.z += a1.z + a2.z + a3.z;
                    acc.w += a1.w + a2.w + a3.w;
                }
            }
            const float hx = bf16rn(nh4.x), hy = bf16rn(nh4.y);
            const float hz = bf16rn(nh4.z), hw = bf16rn(nh4.w);
            Ahi[(2 * lane) * A_STR + rl]     = bf16pack(hx, hy);
            Ahi[(2 * lane + 1) * A_STR + rl] = bf16pack(hz, hw);
            Alo[(2 * lane) * A_STR + rl]     = bf16pack(nh4.x - hx, nh4.y - hy);
            Alo[(2 * lane + 1) * A_STR + rl] = bf16pack(nh4.z - hz, nh4.w - hw);
            const float ax = bf16rn(acc.x), ay = bf16rn(acc.y);
            const float az = bf16rn(acc.z), aw = bf16rn(acc.w);
            Ahi[(64 + 2 * lane) * A_STR + rl] = bf16pack(ax, ay);
            Ahi[(65 + 2 * lane) * A_STR + rl] = bf16pack(az, aw);
            Alo[(64 + 2 * lane) * A_STR + rl] = bf16pack(acc.x - ax, acc.y - ay);
            Alo[(65 + 2 * lane) * A_STR + rl] = bf16pack(acc.z - az, acc.w - aw);
        }
        __syncthreads();

        // ---- MMA mainloop: C[2 n-tiles][4] ----
        float c[2][4];
        #pragma unroll
        for (int nt = 0; nt < 2; nt++)
            c[nt][0] = c[nt][1] = c[nt][2] = c[nt][3] = 0.f;

        #pragma unroll 2
        for (int k = 0; k < 16; k++) {
            const int kp0 = 8 * k + t4;
            const uint32_t ah0 = Ahi[kp0 * A_STR + roffL + g];
            const uint32_t ah1 = Ahi[kp0 * A_STR + roffL + g + 8];
            const uint32_t ah2 = Ahi[(kp0 + 4) * A_STR + roffL + g];
            const uint32_t ah3 = Ahi[(kp0 + 4) * A_STR + roffL + g + 8];
            const uint32_t al0 = Alo[kp0 * A_STR + roffL + g];
            const uint32_t al1 = Alo[kp0 * A_STR + roffL + g + 8];
            const uint32_t al2 = Alo[(kp0 + 4) * A_STR + roffL + g];
            const uint32_t al3 = Alo[(kp0 + 4) * A_STR + roffL + g + 8];
            const uint32_t* B0h = Bhi + kp0 * B_STR + noff + g;
            const uint32_t* B1h = Bhi + (kp0 + 4) * B_STR + noff + g;
            const uint32_t* B0l = Blo + kp0 * B_STR + noff + g;
            const uint32_t* B1l = Blo + (kp0 + 4) * B_STR + noff + g;
            #pragma unroll
            for (int nt = 0; nt < 2; nt++) {
                const uint32_t bh0 = B0h[nt * 8];
                const uint32_t bh1 = B1h[nt * 8];
                const uint32_t bl0 = B0l[nt * 8];
                const uint32_t bl1 = B1l[nt * 8];
                mma16816(c[nt], ah0, ah1, ah2, ah3, bh0, bh1);
                mma16816(c[nt], ah0, ah1, ah2, ah3, bl0, bl1);
                mma16816(c[nt], al0, al1, al2, al3, bh0, bh1);
            }
        }

        // ---- epilogue ----
        const int lr0 = roffL + g;
        const int lr1 = roffL + g + 8;
        const size_t gr0 = (size_t)r0 + min(lr0, nrows - 1);
        const size_t gr1 = (size_t)r0 + min(lr1, nrows - 1);
        const int colh0 = cgrp * 8 + t4;

        float2 v0[2], v1[2];
        float s0 = 0.f, ss0 = 0.f, s1r = 0.f, ss1r = 0.f;
        #pragma unroll
        for (int nt = 0; nt < 2; nt++) {
            const int ch = colh0 + nt * 4;
            const float2 res0 = nh2[gr0 * 64 + ch];
            const float2 res1 = nh2[gr1 * 64 + ch];
            const float2 bia  = prm2[ch];
            float2 a0v, a1v;
            a0v.x = c[nt][0] + res0.x + bia.x;
            a0v.y = c[nt][1] + res0.y + bia.y;
            a1v.x = c[nt][2] + res1.x + bia.x;
            a1v.y = c[nt][3] + res1.y + bia.y;
            v0[nt] = a0v;
            v1[nt] = a1v;
            s0  += a0v.x + a0v.y;  ss0  += a0v.x * a0v.x + a0v.y * a0v.y;
            s1r += a1v.x + a1v.y;  ss1r += a1v.x * a1v.x + a1v.y * a1v.y;
        }
        #pragma unroll
        for (int off_ = 1; off_ <= 2; off_ <<= 1) {
            s0   += __shfl_xor_sync(0xffffffffu, s0, off_);
            ss0  += __shfl_xor_sync(0xffffffffu, ss0, off_);
            s1r  += __shfl_xor_sync(0xffffffffu, s1r, off_);
            ss1r += __shfl_xor_sync(0xffffffffu, ss1r, off_);
        }
        if (t4 == 0) {
            red[lr0 * 8 + cgrp] = make_float2(s0, ss0);
            red[lr1 * 8 + cgrp] = make_float2(s1r, ss1r);
        }
        __syncthreads();

        float sum0 = 0.f, sq0 = 0.f, sum1 = 0.f, sq1 = 0.f;
        #pragma unroll
        for (int p = 0; p < 8; p++) {
            const float2 a = red[lr0 * 8 + p];
            const float2 bb = red[lr1 * 8 + p];
            sum0 += a.x;  sq0 += a.y;
            sum1 += bb.x; sq1 += bb.y;
        }
        const float mean0 = sum0 * (1.f / 128.f);
        const float var0  = sq0 * (1.f / 128.f) - mean0 * mean0;
        const float rstd0 = rsqrtf(var0 + 1e-6f);
        const float mean1 = sum1 * (1.f / 128.f);
        const float var1  = sq1 * (1.f / 128.f) - mean1 * mean1;
        const float rstd1 = rsqrtf(var1 + 1e-6f);

        float d0s = 0.f, d0d = 0.f, d1s = 0.f, d1d = 0.f;
        #pragma unroll
        for (int nt = 0; nt < 2; nt++) {
            const int ch = colh0 + nt * 4;
            const float2 sc2 = prm2[64 + ch];
            const float2 bi2 = prm2[128 + ch];
            float2 o0, o1;
            o0.x = fmaxf((v0[nt].x - mean0) * rstd0 * sc2.x + bi2.x, 0.f);
            o0.y = fmaxf((v0[nt].y - mean0) * rstd0 * sc2.y + bi2.y, 0.f);
            o1.x = fmaxf((v1[nt].x - mean1) * rstd1 * sc2.x + bi2.x, 0.f);
            o1.y = fmaxf((v1[nt].y - mean1) * rstd1 * sc2.y + bi2.y, 0.f);
            if (lr0 < nrows) outp2[((size_t)r0 + lr0) * 64 + ch] = o0;
            if (lr1 < nrows) outp2[((size_t)r0 + lr1) * 64 + ch] = o1;
            if (!LAST) {
                const float2 ws2 = prm2[192 + ch];
                const float2 wd2 = prm2[256 + ch];
                d0s += o0.x * ws2.x + o0.y * ws2.y;
                d0d += o0.x * wd2.x + o0.y * wd2.y;
                d1s += o1.x * ws2.x + o1.y * ws2.y;
                d1d += o1.x * wd2.x + o1.y * wd2.y;
            }
        }
        if (!LAST) {
            #pragma unroll
            for (int off_ = 1; off_ <= 2; off_ <<= 1) {
                d0s += __shfl_xor_sync(0xffffffffu, d0s, off_);
                d0d += __shfl_xor_sync(0xffffffffu, d0d, off_);
                d1s += __shfl_xor_sync(0xffffffffu, d1s, off_);
                d1d += __shfl_xor_sync(0xffffffffu, d1d, off_);
            }
            if (t4 == 0) {
                sdp[lr0 * 8 + cgrp] = make_float2(d0s, d0d);
                sdp[lr1 * 8 + cgrp] = make_float2(d1s, d1d);
            }
            __syncthreads();
            if (tid < 64 && tid < nrows) {
                float sx = 0.f, sy = 0.f;
                #pragma unroll
                for (int p = 0; p < 8; p++) {
                    const float2 a = sdp[tid * 8 + p];
                    sx += a.x;
                    sy += a.y;
                }
                sdot_nxt[r0 + tid] = make_float2(sx, sy);
            }
        }
    }
}

extern "C" void kernel_launch(void* const* d_in, const int* in_sizes, int n_in,
                              void* d_out, int out_size)
{
    const float* node_features = (const float*)d_in[0];
    const float* edge_features = (const float*)d_in[1];
    const int*   edge_indices  = (const int*)d_in[2];
    const float* W_node   = (const float*)d_in[3];
    const float* b_node   = (const float*)d_in[4];
    const float* W_edge   = (const float*)d_in[5];
    const float* b_edge   = (const float*)d_in[6];
    const float* W_gnn    = (const float*)d_in[7];
    const float* b_gnn    = (const float*)d_in[8];
    const float* W_top    = (const float*)d_in[9];
    const float* b_top    = (const float*)d_in[10];
    const float* ln_scale = (const float*)d_in[11];
    const float* ln_bias  = (const float*)d_in[12];

    float *nh_a, *nh_b, *agg_base, *escratch, *edot, *wcombo;
    int *cnt, *offp, *cur, *src_csr, *eid_csr;
    float *edot_csr;
    cudaGetSymbolAddress((void**)&nh_a,     g_node_h);
    cudaGetSymbolAddress((void**)&nh_b,     g_node_h2);
    cudaGetSymbolAddress((void**)&agg_base, g_agg_base);
    cudaGetSymbolAddress((void**)&escratch, g_escratch);
    cudaGetSymbolAddress((void**)&edot,     g_edot);
    cudaGetSymbolAddress((void**)&wcombo,   g_wcombo);
    cudaGetSymbolAddress((void**)&cnt,      g_cnt);
    cudaGetSymbolAddress((void**)&offp,     g_off);
    cudaGetSymbolAddress((void**)&cur,      g_cur);
    cudaGetSymbolAddress((void**)&src_csr,  g_src_csr);
    cudaGetSymbolAddress((void**)&eid_csr,  g_eid_csr);
    cudaGetSymbolAddress((void**)&edot_csr, g_edot_csr);

    float* eaggF  = escratch;              // [NN,64] precompute phase
    float* deg    = escratch + NN * 64;    // [NN]
    float2* sdot_a = (float2*)escratch;            // [NN] layer phase
    float2* sdot_b = (float2*)(escratch + 2 * NN); // [NN]

    float* out_node = (float*)d_out;
    float* out_ew   = (float*)d_out + (size_t)NN * H;

    const int* srcp = edge_indices;
    const int* dstp = edge_indices + NE;

    const int smem_e128 = (128 * H + 32 * 128) * 4;
    const int smem_e64  = (64 * H + 32 * 64) * 4;
    cudaFuncSetAttribute((const void*)embed_kernel<128, false, true>,
                         cudaFuncAttributeMaxDynamicSharedMemorySize, smem_e128);
    cudaFuncSetAttribute((const void*)embed_kernel<64, true, false>,
                         cudaFuncAttributeMaxDynamicSharedMemorySize, smem_e64);
    cudaFuncSetAttribute((const void*)gnn_fused_kernel<false>,
                         cudaFuncAttributeMaxDynamicSharedMemorySize, SMEM_TC);
    cudaFuncSetAttribute((const void*)gnn_fused_kernel<true>,
                         cudaFuncAttributeMaxDynamicSharedMemorySize, SMEM_TC);

    // --- one-time precompute + CSR build ---
    combo_kernel<<<1, 64>>>(W_edge, W_top, b_edge, b_top, wcombo);
    zero_kernel<<<(NN * 65 / 4 + 255) / 256, 256>>>((float4*)escratch, NN * 65 / 4);
    zero_kernel<<<(NN / 4 + 255) / 256, 256>>>((float4*)cnt, NN / 4);
    edge_pre_kernel<<<NE / 8, 256>>>(edge_features, dstp, wcombo, eaggF, deg, cnt, edot);
    scan_kernel<<<1, 1024>>>(cnt, offp, cur);
    scatter_kernel<<<(NE + 255) / 256, 256>>>(srcp, dstp, edot, cur,
                                              src_csr, eid_csr, edot_csr);
    embed_kernel<64, true, false><<<512, 256, smem_e64>>>(
        eaggF, W_edge, b_edge, deg, nullptr, agg_base, nullptr, NN);
    embed_kernel<128, false, true><<<512, 256, smem_e128>>>(
        node_features, W_node, b_node, nullptr, W_top, nh_a, sdot_a, NN);

    // --- layers (fused), ping-pong buffers ---
    gnn_fused_kernel<false><<<148, 1024, SMEM_TC>>>(
        nh_a, nh_b, agg_base, offp, src_csr, eid_csr, edot_csr,
        sdot_a, sdot_b,
        W_gnn + (size_t)0 * 256 * H, b_gnn + 0 * H, ln_scale + 0 * H, ln_bias + 0 * H,
        W_top, nullptr, NN);
    gnn_fused_kernel<false><<<148, 1024, SMEM_TC>>>(
        nh_b, nh_a, agg_base, offp, src_csr, eid_csr, edot_csr,
        sdot_b, sdot_a,
        W_gnn + (size_t)1 * 256 * H, b_gnn + 1 * H, ln_scale + 1 * H, ln_bias + 1 * H,
        W_top, nullptr, NN);
    gnn_fused_kernel<true><<<148, 1024, SMEM_TC>>>(
        nh_a, out_node, agg_base, offp, src_csr, eid_csr, edot_csr,
        sdot_a, nullptr,
        W_gnn + (size_t)2 * 256 * H, b_gnn + 2 * H, ln_scale + 2 * H, ln_bias + 2 * H,
        W_top, out_ew, NN);
}

// round 14
// speedup vs baseline: 1.2188x; 1.2188x over previous
#include <cuda_runtime.h>
#include <cuda_bf16.h>
#include <cstdint>

#define NN 50000
#define NE 200000
#define H  128
#define HV4 32   // H/4
#define NCHUNK ((NN + 63) / 64)   // 782

// Scratch (device globals: allocation-free per harness rules)
__device__ float g_node_h[NN * H];        // 25.6 MB  node_h buffer A
__device__ float g_node_h2[NN * H];       // 25.6 MB  node_h buffer B (ping-pong)
__device__ float g_agg_base[NN * H];      // 25.6 MB  Σ edge_h per dst (factorized)
__device__ float g_escratch[NN * 65];     // precompute: eaggF [NN,64] + deg [NN]; layers: sdot_a|sdot_b
__device__ float g_edot[NE];              // folded edge-constant gate logit
__device__ float g_wcombo[65];            // W_edge @ w_top_e (64) + folded bias
// CSR (dst-sorted edge list), built once per call
__device__ int   g_cnt[NN];
__device__ int   g_off[NN + 1];
__device__ int   g_cur[NN];
__device__ int   g_src_csr[NE];
__device__ float g_edot_csr[NE];
__device__ int   g_bsum[256];             // block sums for scan
__device__ int   g_ctr[4];                // dynamic chunk counters (per layer)

__device__ __forceinline__ void fma4(float4& acc, const float4& wv, float s) {
    acc.x += wv.x * s;
    acc.y += wv.y * s;
    acc.z += wv.z * s;
    acc.w += wv.w * s;
}
__device__ __forceinline__ void red_v2(float* p, float a, float b) {
    asm volatile("red.global.add.v2.f32 [%0], {%1,%2};"
                 :: "l"(p), "f"(a), "f"(b) : "memory");
}
__device__ __forceinline__ uint32_t bf16pack(float a, float b) {
    uint32_t r;
    asm("{.reg .b16 x, y; cvt.rn.bf16.f32 x, %1; cvt.rn.bf16.f32 y, %2; mov.b32 %0, {x, y};}"
        : "=r"(r) : "f"(a), "f"(b));
    return r;
}
__device__ __forceinline__ float bf16rn(float x) {
    return __bfloat162float(__float2bfloat16_rn(x));
}
__device__ __forceinline__ void mma16816(float* c,
                                         uint32_t a0, uint32_t a1, uint32_t a2, uint32_t a3,
                                         uint32_t b0, uint32_t b1) {
    asm("mma.sync.aligned.m16n8k16.row.col.f32.bf16.bf16.f32 "
        "{%0,%1,%2,%3}, {%4,%5,%6,%7}, {%8,%9}, {%0,%1,%2,%3};"
        : "+f"(c[0]), "+f"(c[1]), "+f"(c[2]), "+f"(c[3])
        : "r"(a0), "r"(a1), "r"(a2), "r"(a3), "r"(b0), "r"(b1));
}

__global__ void zero_kernel(float4* __restrict__ p, int n4) {
    int i = blockIdx.x * blockDim.x + threadIdx.x;
    if (i < n4) p[i] = make_float4(0.f, 0.f, 0.f, 0.f);
}

// ---------------------------------------------------------------------------
__global__ void combo_kernel(const float* __restrict__ W_edge,
                             const float* __restrict__ W_top,
                             const float* __restrict__ b_edge,
                             const float* __restrict__ b_top,
                             float* __restrict__ wcombo,
                             int* __restrict__ ctr)
{
    const int k = threadIdx.x;   // 64 threads
    float s = 0.f;
    for (int h = 0; h < H; h++) s += W_edge[k * H + h] * W_top[2 * H + h];
    wcombo[k] = s;
    if (k == 0) {
        float b = b_top[0];
        for (int h = 0; h < H; h++) b += b_edge[h] * W_top[2 * H + h];
        wcombo[64] = b;
        ctr[0] = 0; ctr[1] = 0; ctr[2] = 0; ctr[3] = 0;
    }
}

// ---------------------------------------------------------------------------
__global__ void edge_pre_kernel(const float* __restrict__ ef,
                                const int* __restrict__ dst,
                                const float* __restrict__ wcombo,
                                float* __restrict__ eaggF,
                                float* __restrict__ deg,
                                int* __restrict__ cnt,
                                float* __restrict__ edot)
{
    __shared__ float wsh[65];
    const int tid  = threadIdx.x;
    const int lane = tid & 31;
    const int wid  = tid >> 5;
    if (tid < 65) wsh[tid] = wcombo[tid];
    __syncthreads();

    const int e = blockIdx.x * 8 + wid;
    const int d = dst[e];
    float2 v = ((const float2*)ef)[(size_t)e * 32 + lane];
    float p = v.x * wsh[lane * 2] + v.y * wsh[lane * 2 + 1];
    #pragma unroll
    for (int off = 16; off; off >>= 1)
        p += __shfl_xor_sync(0xffffffffu, p, off);
    if (lane == 0) {
        edot[e] = p + wsh[64];
        atomicAdd(deg + d, 1.f);
        atomicAdd(cnt + d, 1);
    }
    red_v2(eaggF + (size_t)d * 64 + lane * 2, v.x, v.y);
}

// ---------------------------------------------------------------------------
// Coalesced 3-phase CSR scan: block sums -> scan of 196 sums -> offsets.
// ---------------------------------------------------------------------------
#define SCAN_BLOCKS ((NN + 255) / 256)   // 196

__global__ void sum_kernel(const int* __restrict__ cnt, int* __restrict__ bsum) {
    const int t = threadIdx.x;
    const int idx = blockIdx.x * 256 + t;
    int v = (idx < NN) ? cnt[idx] : 0;
    #pragma unroll
    for (int off = 16; off; off >>= 1)
        v += __shfl_xor_sync(0xffffffffu, v, off);
    __shared__ int ws[8];
    if ((t & 31) == 0) ws[t >> 5] = v;
    __syncthreads();
    if (t == 0) {
        int s = 0;
        #pragma unroll
        for (int i = 0; i < 8; i++) s += ws[i];
        bsum[blockIdx.x] = s;
    }
}

__global__ void scanb_kernel(int* __restrict__ bsum) {
    // single block of 256: in-place exclusive scan of SCAN_BLOCKS entries
    __shared__ int sh[256];
    const int t = threadIdx.x;
    sh[t] = (t < SCAN_BLOCKS) ? bsum[t] : 0;
    __syncthreads();
    int x = sh[t];
    for (int d = 1; d < 256; d <<= 1) {
        int y = (t >= d) ? sh[t - d] : 0;
        __syncthreads();
        x += y;
        sh[t] = x;
        __syncthreads();
    }
    if (t < SCAN_BLOCKS) bsum[t] = (t == 0) ? 0 : sh[t - 1];
}

__global__ void offsets_kernel(const int* __restrict__ cnt,
                               const int* __restrict__ bsum,
                               int* __restrict__ off,
                               int* __restrict__ cur)
{
    const int t = threadIdx.x;
    const int idx = blockIdx.x * 256 + t;
    const int c = (idx < NN) ? cnt[idx] : 0;
    // inclusive warp scan
    int x = c;
    #pragma unroll
    for (int d = 1; d < 32; d <<= 1) {
        int y = __shfl_up_sync(0xffffffffu, x, d);
        if ((t & 31) >= d) x += y;
    }
    __shared__ int ws[8];
    if ((t & 31) == 31) ws[t >> 5] = x;
    __syncthreads();
    if (t < 8) {
        int v = ws[t];
        #pragma unroll
        for (int d = 1; d < 8; d <<= 1) {
            int y = __shfl_up_sync(0xffu, v, d);
            if (t >= d) v += y;
        }
        ws[t] = v;  // inclusive over warp sums
    }
    __syncthreads();
    const int wpre = (t >> 5) ? ws[(t >> 5) - 1] : 0;
    const int excl = x - c + wpre + bsum[blockIdx.x];
    if (idx < NN) {
        off[idx] = excl;
        cur[idx] = excl;
        if (idx == NN - 1) off[NN] = NE;
    }
}

__global__ void scatter_kernel(const int* __restrict__ src,
                               const int* __restrict__ dst,
                               const float* __restrict__ edot,
                               int* __restrict__ cur,
                               int* __restrict__ src_csr,
                               float* __restrict__ edot_csr)
{
    const int e = blockIdx.x * 256 + threadIdx.x;
    if (e >= NE) return;
    const int d = dst[e];
    const int pos = atomicAdd(cur + d, 1);
    src_csr[pos]  = src[e];
    edot_csr[pos] = edot[e];
}

// ---------------------------------------------------------------------------
// Final edge weights, coalesced by original edge id (uses post-layer-1 sdot).
// ---------------------------------------------------------------------------
__global__ void ew_kernel(const int* __restrict__ src,
                          const int* __restrict__ dst,
                          const float* __restrict__ edot,
                          const float2* __restrict__ sdot,
                          float* __restrict__ ew)
{
    const int e = blockIdx.x * 256 + threadIdx.x;
    if (e >= NE) return;
    const float p = sdot[src[e]].x + sdot[dst[e]].y + edot[e];
    ew[e] = 1.f / (1.f + __expf(-p));
}

// ---------------------------------------------------------------------------
// Embed GEMM (R3-proven): out[rows,H] = X[rows,K] @ W[K,H] + scale*b
// ---------------------------------------------------------------------------
template<int K, bool DEGBIAS, bool SDOT>
__global__ void embed_kernel(const float* __restrict__ X,
                             const float* __restrict__ W,
                             const float* __restrict__ b,
                             const float* __restrict__ deg,
                             const float* __restrict__ W_top,
                             float* __restrict__ out,
                             float2* __restrict__ sdot2, int rows)
{
    extern __shared__ float sm[];
    float* Wsh  = sm;            // K*H floats
    float* xbuf = sm + K * H;    // 32*K floats

    const int tid  = threadIdx.x;
    const int lane = tid & 31;
    const int wid  = tid >> 5;

    for (int i = tid; i < K * H / 4; i += 256)
        ((float4*)Wsh)[i] = ((const float4*)W)[i];
    const float4 bias = ((const float4*)b)[lane];
    float4 wsA, wdA;
    if (SDOT) {
        wsA = ((const float4*)W_top)[lane];
        wdA = ((const float4*)W_top)[32 + lane];
    }

    for (int r0 = blockIdx.x * 32; r0 < rows; r0 += gridDim.x * 32) {
        __syncthreads();
        const int nrows = min(32, rows - r0);
        for (int i = tid; i < nrows * (K / 4); i += 256)
            ((float4*)xbuf)[i] = ((const float4*)(X + (size_t)r0 * K))[i];
        __syncthreads();

        const int rbase = wid * 4;
        if (rbase < nrows) {
            float4 acc0 = make_float4(0.f, 0.f, 0.f, 0.f);
            float4 acc1 = acc0, acc2 = acc0, acc3 = acc0;
            const float* xr0 = xbuf + (rbase + 0) * K;
            const float* xr1 = xbuf + (rbase + 1) * K;
            const float* xr2 = xbuf + (rbase + 2) * K;
            const float* xr3 = xbuf + (rbase + 3) * K;
            #pragma unroll 4
            for (int k = 0; k < K; k++) {
                float4 wv = ((float4*)Wsh)[k * HV4 + lane];
                fma4(acc0, wv, xr0[k]);
                fma4(acc1, wv, xr1[k]);
                fma4(acc2, wv, xr2[k]);
                fma4(acc3, wv, xr3[k]);
            }
            float4 accs[4] = {acc0, acc1, acc2, acc3};
            #pragma unroll
            for (int rr = 0; rr < 4; rr++) {
                const float scb = DEGBIAS ? deg[r0 + rbase + rr] : 1.f;
                float4 o;
                o.x = accs[rr].x + scb * bias.x;
                o.y = accs[rr].y + scb * bias.y;
                o.z = accs[rr].z + scb * bias.z;
                o.w = accs[rr].w + scb * bias.w;
                ((float4*)out)[(size_t)(r0 + rbase + rr) * HV4 + lane] = o;
                if (SDOT) {
                    float s1 = o.x * wsA.x + o.y * wsA.y + o.z * wsA.z + o.w * wsA.w;
                    float s2 = o.x * wdA.x + o.y * wdA.y + o.z * wdA.z + o.w * wdA.w;
                    #pragma unroll
                    for (int off = 16; off; off >>= 1) {
                        s1 += __shfl_xor_sync(0xffffffffu, s1, off);
                        s2 += __shfl_xor_sync(0xffffffffu, s2, off);
                    }
                    if (lane == 0) sdot2[r0 + rbase + rr] = make_float2(s1, s2);
                }
            }
        }
    }
}

// ---------------------------------------------------------------------------
// Fused GNN layer (R11-proven 512-thread core) + dynamic chunk scheduling.
// ---------------------------------------------------------------------------
#define A_STR 73
#define B_STR 136
#define A_PLANE (128 * A_STR)
#define B_PLANE (128 * B_STR)
#define SMEM_TC ((2 * A_PLANE + 2 * B_PLANE + 640 + 1024 + 1024 + 4) * 4)

template<bool LAST>
__global__ void __launch_bounds__(512, 1)
gnn_fused_kernel(const float* __restrict__ nh_old,
                 float* __restrict__ nh_new,
                 const float* __restrict__ agg_base,
                 const int* __restrict__ off,
                 const int* __restrict__ src_csr,
                 const float* __restrict__ edot_csr,
                 const float2* __restrict__ sdot_cur,
                 float2* __restrict__ sdot_nxt,
                 const float* __restrict__ W,      // [256,128]
                 const float* __restrict__ b,
                 const float* __restrict__ lns,
                 const float* __restrict__ lnb,
                 const float* __restrict__ W_top,
                 int* __restrict__ ctr, int rows)
{
    extern __shared__ uint32_t smu[];
    uint32_t* Ahi = smu;
    uint32_t* Alo = Ahi + A_PLANE;
    uint32_t* Bhi = Alo + A_PLANE;
    uint32_t* Blo = Bhi + B_PLANE;
    float*    prm = (float*)(Blo + B_PLANE);        // 640 floats: b|lns|lnb|ws|wd
    float2*   red = (float2*)(prm + 640);           // [64 rows][4 col-partials]
    float2*   sdp = red + 256;                      // [64 rows][4 col-partials]
    int*      s_chunk = (int*)(sdp + 256);

    const int tid  = threadIdx.x;
    const int lane = tid & 31;
    const int w    = tid >> 5;
    const int t4   = lane & 3;
    const int g    = lane >> 2;

    const float2* nh2   = (const float2*)nh_old;
    float2*       outp2 = (float2*)nh_new;
    const float2* prm2  = (const float2*)prm;

    // ---- stage W (once): packed bf16x2 hi/lo planes ----
    for (int i = tid; i < 128 * 128; i += 512) {
        const int kp = i >> 7, n = i & 127;
        const float w0 = W[(size_t)(2 * kp) * 128 + n];
        const float w1 = W[(size_t)(2 * kp + 1) * 128 + n];
        const float h0 = bf16rn(w0);
        const float h1 = bf16rn(w1);
        Bhi[kp * B_STR + n] = bf16pack(h0, h1);
        Blo[kp * B_STR + n] = bf16pack(w0 - h0, w1 - h1);
    }
    for (int i = tid; i < 128; i += 512) {
        prm[i]       = b[i];
        prm[128 + i] = lns[i];
        prm[256 + i] = lnb[i];
        prm[384 + i] = W_top[i];
        prm[512 + i] = W_top[128 + i];
    }

    const int roffL = (w >> 2) * 16;     // row group: 0/16/32/48
    const int noff  = (w & 3) * 32;      // col group: 0/32/64/96
    const int cgrp  = w & 3;

    for (;;) {
        __syncthreads();   // protect prior chunk's smem + W staging on first iter
        if (tid == 0) *s_chunk = atomicAdd(ctr, 1);
        __syncthreads();
        const int chunk = *s_chunk;
        if (chunk >= NCHUNK) break;
        const int r0 = chunk * 64;
        const int nrows = min(64, rows - r0);

        // ---- stage + aggregate: warp owns nodes w*4 .. w*4+3 ----
        for (int q = 0; q < 4; q++) {
            const int rl = w * 4 + q;
            float4 nh4 = make_float4(0.f, 0.f, 0.f, 0.f);
            float4 acc = make_float4(0.f, 0.f, 0.f, 0.f);
            if (rl < nrows) {
                const int node = r0 + rl;
                nh4 = ((const float4*)nh_old)[(size_t)node * HV4 + lane];
                acc = ((const float4*)agg_base)[(size_t)node * HV4 + lane];
                const float sdy = sdot_cur[node].y;
                const int beg = off[node], end = off[node + 1];
                for (int jb = beg; jb < end; jb += 32) {
                    const int j = jb + lane;
                    float wgt = 0.f;
                    int   sj  = 0;
                    if (j < end) {
                        sj = src_csr[j];
                        const float p = sdot_cur[sj].x + sdy + edot_csr[j];
                        wgt = 1.f / (1.f + __expf(-p));
                    }
                    const int m = min(32, end - jb);
                    float4 a1 = make_float4(0.f, 0.f, 0.f, 0.f);
                    float4 a2 = a1, a3 = a1;
                    int jj = 0;
                    for (; jj + 4 <= m; jj += 4) {
                        const int s0 = __shfl_sync(0xffffffffu, sj, jj);
                        const int s1 = __shfl_sync(0xffffffffu, sj, jj + 1);
                        const int s2 = __shfl_sync(0xffffffffu, sj, jj + 2);
                        const int s3 = __shfl_sync(0xffffffffu, sj, jj + 3);
                        const float w0 = __shfl_sync(0xffffffffu, wgt, jj);
                        const float w1 = __shfl_sync(0xffffffffu, wgt, jj + 1);
                        const float w2 = __shfl_sync(0xffffffffu, wgt, jj + 2);
                        const float w3 = __shfl_sync(0xffffffffu, wgt, jj + 3);
                        const float4 f0 = ((const float4*)nh_old)[(size_t)s0 * HV4 + lane];
                        const float4 f1 = ((const float4*)nh_old)[(size_t)s1 * HV4 + lane];
                        const float4 f2 = ((const float4*)nh_old)[(size_t)s2 * HV4 + lane];
                        const float4 f3 = ((const float4*)nh_old)[(size_t)s3 * HV4 + lane];
                        fma4(acc, f0, w0);
                        fma4(a1, f1, w1);
                        fma4(a2, f2, w2);
                        fma4(a3, f3, w3);
                    }
                    for (; jj < m; jj++) {
                        const int s0 = __shfl_sync(0xffffffffu, sj, jj);
                        const float w0 = __shfl_sync(0xffffffffu, wgt, jj);
                        const float4 f0 = ((const float4*)nh_old)[(size_t)s0 * HV4 + lane];
                        fma4(acc, f0, w0);
                    }
                    acc.x += a1.x + a2.x + a3.x;
                    acc.y += a1.y + a2.y + a3.y;
                    acc.z += a1.z + a2.z + a3.z;
                    acc.w += a1.w + a2.w + a3.w;
                }
            }
            const float hx = bf16rn(nh4.x), hy = bf16rn(nh4.y);
            const float hz = bf16rn(nh4.z), hw = bf16rn(nh4.w);
            Ahi[(2 * lane) * A_STR + rl]     = bf16pack(hx, hy);
            Ahi[(2 * lane + 1) * A_STR + rl] = bf16pack(hz, hw);
            Alo[(2 * lane) * A_STR + rl]     = bf16pack(nh4.x - hx, nh4.y - hy);
            Alo[(2 * lane + 1) * A_STR + rl] = bf16pack(nh4.z - hz, nh4.w - hw);
            const float ax = bf16rn(acc.x), ay = bf16rn(acc.y);
            const float az = bf16rn(acc.z), aw = bf16rn(acc.w);
            Ahi[(64 + 2 * lane) * A_STR + rl] = bf16pack(ax, ay);
            Ahi[(65 + 2 * lane) * A_STR + rl] = bf16pack(az, aw);
            Alo[(64 + 2 * lane) * A_STR + rl] = bf16pack(acc.x - ax, acc.y - ay);
            Alo[(65 + 2 * lane) * A_STR + rl] = bf16pack(acc.z - az, acc.w - aw);
        }
        __syncthreads();

        // ---- MMA mainloop: C[4 n-tiles][4] ----
        float c[4][4];
        #pragma unroll
        for (int nt = 0; nt < 4; nt++)
            c[nt][0] = c[nt][1] = c[nt][2] = c[nt][3] = 0.f;

        #pragma unroll 2
        for (int k = 0; k < 16; k++) {
            const int kp0 = 8 * k + t4;
            const uint32_t ah0 = Ahi[kp0 * A_STR + roffL + g];
            const uint32_t ah1 = Ahi[kp0 * A_STR + roffL + g + 8];
            const uint32_t ah2 = Ahi[(kp0 + 4) * A_STR + roffL + g];
            const uint32_t ah3 = Ahi[(kp0 + 4) * A_STR + roffL + g + 8];
            const uint32_t al0 = Alo[kp0 * A_STR + roffL + g];
            const uint32_t al1 = Alo[kp0 * A_STR + roffL + g + 8];
            const uint32_t al2 = Alo[(kp0 + 4) * A_STR + roffL + g];
            const uint32_t al3 = Alo[(kp0 + 4) * A_STR + roffL + g + 8];
            const uint32_t* B0h = Bhi + kp0 * B_STR + noff + g;
            const uint32_t* B1h = Bhi + (kp0 + 4) * B_STR + noff + g;
            const uint32_t* B0l = Blo + kp0 * B_STR + noff + g;
            const uint32_t* B1l = Blo + (kp0 + 4) * B_STR + noff + g;
            #pragma unroll
            for (int nt = 0; nt < 4; nt++) {
                const uint32_t bh0 = B0h[nt * 8];
                const uint32_t bh1 = B1h[nt * 8];
                const uint32_t bl0 = B0l[nt * 8];
                const uint32_t bl1 = B1l[nt * 8];
                mma16816(c[nt], ah0, ah1, ah2, ah3, bh0, bh1);
                mma16816(c[nt], ah0, ah1, ah2, ah3, bl0, bl1);
                mma16816(c[nt], al0, al1, al2, al3, bh0, bh1);
            }
        }

        // ---- epilogue ----
        const int lr0 = roffL + g;
        const int lr1 = roffL + g + 8;
        const size_t gr0 = (size_t)r0 + min(lr0, nrows - 1);
        const size_t gr1 = (size_t)r0 + min(lr1, nrows - 1);
        const int colh0 = cgrp * 16 + t4;

        float2 v0[4], v1[4];
        float s0 = 0.f, ss0 = 0.f, s1r = 0.f, ss1r = 0.f;
        #pragma unroll
        for (int nt = 0; nt < 4; nt++) {
            const int ch = colh0 + nt * 4;
            const float2 res0 = nh2[gr0 * 64 + ch];
            const float2 res1 = nh2[gr1 * 64 + ch];
            const float2 bia  = prm2[ch];
            float2 a0v, a1v;
            a0v.x = c[nt][0] + res0.x + bia.x;
            a0v.y = c[nt][1] + res0.y + bia.y;
            a1v.x = c[nt][2] + res1.x + bia.x;
            a1v.y = c[nt][3] + res1.y + bia.y;
            v0[nt] = a0v;
            v1[nt] = a1v;
            s0  += a0v.x + a0v.y;  ss0  += a0v.x * a0v.x + a0v.y * a0v.y;
            s1r += a1v.x + a1v.y;  ss1r += a1v.x * a1v.x + a1v.y * a1v.y;
        }
        #pragma unroll
        for (int off_ = 1; off_ <= 2; off_ <<= 1) {
            s0   += __shfl_xor_sync(0xffffffffu, s0, off_);
            ss0  += __shfl_xor_sync(0xffffffffu, ss0, off_);
            s1r  += __shfl_xor_sync(0xffffffffu, s1r, off_);
            ss1r += __shfl_xor_sync(0xffffffffu, ss1r, off_);
        }
        if (t4 == 0) {
            red[lr0 * 4 + cgrp] = make_float2(s0, ss0);
            red[lr1 * 4 + cgrp] = make_float2(s1r, ss1r);
        }
        __syncthreads();

        float sum0 = 0.f, sq0 = 0.f, sum1 = 0.f, sq1 = 0.f;
        #pragma unroll
        for (int p = 0; p < 4; p++) {
            const float2 a = red[lr0 * 4 + p];
            const float2 bb = red[lr1 * 4 + p];
            sum0 += a.x;  sq0 += a.y;
            sum1 += bb.x; sq1 += bb.y;
        }
        const float mean0 = sum0 * (1.f / 128.f);
        const float var0  = sq0 * (1.f / 128.f) - mean0 * mean0;
        const float rstd0 = rsqrtf(var0 + 1e-6f);
        const float mean1 = sum1 * (1.f / 128.f);
        const float var1  = sq1 * (1.f / 128.f) - mean1 * mean1;
        const float rstd1 = rsqrtf(var1 + 1e-6f);

        float d0s = 0.f, d0d = 0.f, d1s = 0.f, d1d = 0.f;
        #pragma unroll
        for (int nt = 0; nt < 4; nt++) {
            const int ch = colh0 + nt * 4;
            const float2 sc2 = prm2[64 + ch];
            const float2 bi2 = prm2[128 + ch];
            float2 o0, o1;
            o0.x = fmaxf((v0[nt].x - mean0) * rstd0 * sc2.x + bi2.x, 0.f);
            o0.y = fmaxf((v0[nt].y - mean0) * rstd0 * sc2.y + bi2.y, 0.f);
            o1.x = fmaxf((v1[nt].x - mean1) * rstd1 * sc2.x + bi2.x, 0.f);
            o1.y = fmaxf((v1[nt].y - mean1) * rstd1 * sc2.y + bi2.y, 0.f);
            if (lr0 < nrows) outp2[((size_t)r0 + lr0) * 64 + ch] = o0;
            if (lr1 < nrows) outp2[((size_t)r0 + lr1) * 64 + ch] = o1;
            if (!LAST) {
                const float2 ws2 = prm2[192 + ch];
                const float2 wd2 = prm2[256 + ch];
                d0s += o0.x * ws2.x + o0.y * ws2.y;
                d0d += o0.x * wd2.x + o0.y * wd2.y;
                d1s += o1.x * ws2.x + o1.y * ws2.y;
                d1d += o1.x * wd2.x + o1.y * wd2.y;
            }
        }
        if (!LAST) {
            #pragma unroll
            for (int off_ = 1; off_ <= 2; off_ <<= 1) {
                d0s += __shfl_xor_sync(0xffffffffu, d0s, off_);
                d0d += __shfl_xor_sync(0xffffffffu, d0d, off_);
                d1s += __shfl_xor_sync(0xffffffffu, d1s, off_);
                d1d += __shfl_xor_sync(0xffffffffu, d1d, off_);
            }
            if (t4 == 0) {
                sdp[lr0 * 4 + cgrp] = make_float2(d0s, d0d);
                sdp[lr1 * 4 + cgrp] = make_float2(d1s, d1d);
            }
            __syncthreads();
            if (tid < 64 && tid < nrows) {
                float sx = 0.f, sy = 0.f;
                #pragma unroll
                for (int p = 0; p < 4; p++) {
                    const float2 a = sdp[tid * 4 + p];
                    sx += a.x;
                    sy += a.y;
                }
                sdot_nxt[r0 + tid] = make_float2(sx, sy);
            }
        }
    }
}

extern "C" void kernel_launch(void* const* d_in, const int* in_sizes, int n_in,
                              void* d_out, int out_size)
{
    const float* node_features = (const float*)d_in[0];
    const float* edge_features = (const float*)d_in[1];
    const int*   edge_indices  = (const int*)d_in[2];
    const float* W_node   = (const float*)d_in[3];
    const float* b_node   = (const float*)d_in[4];
    const float* W_edge   = (const float*)d_in[5];
    const float* b_edge   = (const float*)d_in[6];
    const float* W_gnn    = (const float*)d_in[7];
    const float* b_gnn    = (const float*)d_in[8];
    const float* W_top    = (const float*)d_in[9];
    const float* b_top    = (const float*)d_in[10];
    const float* ln_scale = (const float*)d_in[11];
    const float* ln_bias  = (const float*)d_in[12];

    float *nh_a, *nh_b, *agg_base, *escratch, *edot, *wcombo;
    int *cnt, *offp, *cur, *src_csr, *bsum, *ctr;
    float *edot_csr;
    cudaGetSymbolAddress((void**)&nh_a,     g_node_h);
    cudaGetSymbolAddress((void**)&nh_b,     g_node_h2);
    cudaGetSymbolAddress((void**)&agg_base, g_agg_base);
    cudaGetSymbolAddress((void**)&escratch, g_escratch);
    cudaGetSymbolAddress((void**)&edot,     g_edot);
    cudaGetSymbolAddress((void**)&wcombo,   g_wcombo);
    cudaGetSymbolAddress((void**)&cnt,      g_cnt);
    cudaGetSymbolAddress((void**)&offp,     g_off);
    cudaGetSymbolAddress((void**)&cur,      g_cur);
    cudaGetSymbolAddress((void**)&src_csr,  g_src_csr);
    cudaGetSymbolAddress((void**)&bsum,     g_bsum);
    cudaGetSymbolAddress((void**)&ctr,      g_ctr);
    cudaGetSymbolAddress((void**)&edot_csr, g_edot_csr);

    float* eaggF  = escratch;              // [NN,64] precompute phase
    float* deg    = escratch + NN * 64;    // [NN]
    float2* sdot_a = (float2*)escratch;            // [NN] layer phase
    float2* sdot_b = (float2*)(escratch + 2 * NN); // [NN]

    float* out_node = (float*)d_out;
    float* out_ew   = (float*)d_out + (size_t)NN * H;

    const int* srcp = edge_indices;
    const int* dstp = edge_indices + NE;

    const int smem_e128 = (128 * H + 32 * 128) * 4;
    const int smem_e64  = (64 * H + 32 * 64) * 4;
    cudaFuncSetAttribute((const void*)embed_kernel<128, false, true>,
                         cudaFuncAttributeMaxDynamicSharedMemorySize, smem_e128);
    cudaFuncSetAttribute((const void*)embed_kernel<64, true, false>,
                         cudaFuncAttributeMaxDynamicSharedMemorySize, smem_e64);
    cudaFuncSetAttribute((const void*)gnn_fused_kernel<false>,
                         cudaFuncAttributeMaxDynamicSharedMemorySize, SMEM_TC);
    cudaFuncSetAttribute((const void*)gnn_fused_kernel<true>,
                         cudaFuncAttributeMaxDynamicSharedMemorySize, SMEM_TC);

    // --- one-time precompute + CSR build ---
    combo_kernel<<<1, 64>>>(W_edge, W_top, b_edge, b_top, wcombo, ctr);
    zero_kernel<<<(NN * 65 / 4 + 255) / 256, 256>>>((float4*)escratch, NN * 65 / 4);
    zero_kernel<<<(NN / 4 + 255) / 256, 256>>>((float4*)cnt, NN / 4);
    edge_pre_kernel<<<NE / 8, 256>>>(edge_features, dstp, wcombo, eaggF, deg, cnt, edot);
    sum_kernel<<<SCAN_BLOCKS, 256>>>(cnt, bsum);
    scanb_kernel<<<1, 256>>>(bsum);
    offsets_kernel<<<SCAN_BLOCKS, 256>>>(cnt, bsum, offp, cur);
    scatter_kernel<<<(NE + 255) / 256, 256>>>(srcp, dstp, edot, cur, src_csr, edot_csr);
    embed_kernel<64, true, false><<<512, 256, smem_e64>>>(
        eaggF, W_edge, b_edge, deg, nullptr, agg_base, nullptr, NN);
    embed_kernel<128, false, true><<<512, 256, smem_e128>>>(
        node_features, W_node, b_node, nullptr, W_top, nh_a, sdot_a, NN);

    // --- layers (fused), ping-pong buffers, dynamic scheduling ---
    gnn_fused_kernel<false><<<148, 512, SMEM_TC>>>(
        nh_a, nh_b, agg_base, offp, src_csr, edot_csr,
        sdot_a, sdot_b,
        W_gnn + (size_t)0 * 256 * H, b_gnn + 0 * H, ln_scale + 0 * H, ln_bias + 0 * H,
        W_top, ctr + 0, NN);
    gnn_fused_kernel<false><<<148, 512, SMEM_TC>>>(
        nh_b, nh_a, agg_base, offp, src_csr, edot_csr,
        sdot_b, sdot_a,
        W_gnn + (size_t)1 * 256 * H, b_gnn + 1 * H, ln_scale + 1 * H, ln_bias + 1 * H,
        W_top, ctr + 1, NN);
    ew_kernel<<<(NE + 255) / 256, 256>>>(srcp, dstp, edot, sdot_a, out_ew);
    gnn_fused_kernel<true><<<148, 512, SMEM_TC>>>(
        nh_a, out_node, agg_base, offp, src_csr, edot_csr,
        sdot_a, nullptr,
        W_gnn + (size_t)2 * 256 * H, b_gnn + 2 * H, ln_scale + 2 * H, ln_bias + 2 * H,
        W_top, ctr + 2, NN);
}

// round 16
// speedup vs baseline: 1.3099x; 1.0747x over previous
#include <cuda_runtime.h>
#include <cuda_bf16.h>
#include <cstdint>

#define NN 50000
#define NE 200000
#define H  128
#define HV4 32   // H/4
#define NCHUNK ((NN + 63) / 64)   // 782

// Scratch (device globals: allocation-free per harness rules)
__device__ float g_node_h[NN * H];        // 25.6 MB  node_h buffer A
__device__ float g_node_h2[NN * H];       // 25.6 MB  node_h buffer B (ping-pong)
__device__ float g_agg_base[NN * H];      // 25.6 MB  Σ edge_h per dst (factorized)
__device__ float g_escratch[NN * 65];     // precompute: eaggF [NN,64] + deg [NN]; layers: sdot_a|sdot_b
__device__ float g_edot[NE];              // folded edge-constant gate logit
__device__ float g_wcombo[65];            // W_edge @ w_top_e (64) + folded bias
// CSR (dst-sorted edge list), built once per call
__device__ int   g_cnt[NN];
__device__ int   g_off[NN + 1];
__device__ int   g_cur[NN];
__device__ int   g_src_csr[NE];
__device__ float g_edot_csr[NE];
__device__ int   g_bsum[256];             // block sums for scan
__device__ int   g_ctr[4];                // dynamic chunk counters (per layer)

__device__ __forceinline__ void fma4(float4& acc, const float4& wv, float s) {
    acc.x += wv.x * s;
    acc.y += wv.y * s;
    acc.z += wv.z * s;
    acc.w += wv.w * s;
}
__device__ __forceinline__ void red_v2(float* p, float a, float b) {
    asm volatile("red.global.add.v2.f32 [%0], {%1,%2};"
                 :: "l"(p), "f"(a), "f"(b) : "memory");
}
__device__ __forceinline__ uint32_t bf16pack(float a, float b) {
    uint32_t r;
    asm("{.reg .b16 x, y; cvt.rn.bf16.f32 x, %1; cvt.rn.bf16.f32 y, %2; mov.b32 %0, {x, y};}"
        : "=r"(r) : "f"(a), "f"(b));
    return r;
}
__device__ __forceinline__ float bf16rn(float x) {
    return __bfloat162float(__float2bfloat16_rn(x));
}
__device__ __forceinline__ void mma16816(float* c,
                                         uint32_t a0, uint32_t a1, uint32_t a2, uint32_t a3,
                                         uint32_t b0, uint32_t b1) {
    asm("mma.sync.aligned.m16n8k16.row.col.f32.bf16.bf16.f32 "
        "{%0,%1,%2,%3}, {%4,%5,%6,%7}, {%8,%9}, {%0,%1,%2,%3};"
        : "+f"(c[0]), "+f"(c[1]), "+f"(c[2]), "+f"(c[3])
        : "r"(a0), "r"(a1), "r"(a2), "r"(a3), "r"(b0), "r"(b1));
}

__global__ void zero_kernel(float4* __restrict__ p, int n4) {
    int i = blockIdx.x * blockDim.x + threadIdx.x;
    if (i < n4) p[i] = make_float4(0.f, 0.f, 0.f, 0.f);
}

// ---------------------------------------------------------------------------
__global__ void combo_kernel(const float* __restrict__ W_edge,
                             const float* __restrict__ W_top,
                             const float* __restrict__ b_edge,
                             const float* __restrict__ b_top,
                             float* __restrict__ wcombo,
                             int* __restrict__ ctr)
{
    const int k = threadIdx.x;   // 64 threads
    float s = 0.f;
    for (int h = 0; h < H; h++) s += W_edge[k * H + h] * W_top[2 * H + h];
    wcombo[k] = s;
    if (k == 0) {
        float b = b_top[0];
        for (int h = 0; h < H; h++) b += b_edge[h] * W_top[2 * H + h];
        wcombo[64] = b;
        ctr[0] = 0; ctr[1] = 0; ctr[2] = 0; ctr[3] = 0;
    }
}

// ---------------------------------------------------------------------------
__global__ void edge_pre_kernel(const float* __restrict__ ef,
                                const int* __restrict__ dst,
                                const float* __restrict__ wcombo,
                                float* __restrict__ eaggF,
                                float* __restrict__ deg,
                                int* __restrict__ cnt,
                                float* __restrict__ edot)
{
    __shared__ float wsh[65];
    const int tid  = threadIdx.x;
    const int lane = tid & 31;
    const int wid  = tid >> 5;
    if (tid < 65) wsh[tid] = wcombo[tid];
    __syncthreads();

    const int e = blockIdx.x * 8 + wid;
    const int d = dst[e];
    float2 v = ((const float2*)ef)[(size_t)e * 32 + lane];
    float p = v.x * wsh[lane * 2] + v.y * wsh[lane * 2 + 1];
    #pragma unroll
    for (int off = 16; off; off >>= 1)
        p += __shfl_xor_sync(0xffffffffu, p, off);
    if (lane == 0) {
        edot[e] = p + wsh[64];
        atomicAdd(deg + d, 1.f);
        atomicAdd(cnt + d, 1);
    }
    red_v2(eaggF + (size_t)d * 64 + lane * 2, v.x, v.y);
}

// ---------------------------------------------------------------------------
// Coalesced 3-phase CSR scan: block sums -> scan of 196 sums -> offsets.
// ---------------------------------------------------------------------------
#define SCAN_BLOCKS ((NN + 255) / 256)   // 196

__global__ void sum_kernel(const int* __restrict__ cnt, int* __restrict__ bsum) {
    const int t = threadIdx.x;
    const int idx = blockIdx.x * 256 + t;
    int v = (idx < NN) ? cnt[idx] : 0;
    #pragma unroll
    for (int off = 16; off; off >>= 1)
        v += __shfl_xor_sync(0xffffffffu, v, off);
    __shared__ int ws[8];
    if ((t & 31) == 0) ws[t >> 5] = v;
    __syncthreads();
    if (t == 0) {
        int s = 0;
        #pragma unroll
        for (int i = 0; i < 8; i++) s += ws[i];
        bsum[blockIdx.x] = s;
    }
}

__global__ void scanb_kernel(int* __restrict__ bsum) {
    __shared__ int sh[256];
    const int t = threadIdx.x;
    sh[t] = (t < SCAN_BLOCKS) ? bsum[t] : 0;
    __syncthreads();
    int x = sh[t];
    for (int d = 1; d < 256; d <<= 1) {
        int y = (t >= d) ? sh[t - d] : 0;
        __syncthreads();
        x += y;
        sh[t] = x;
        __syncthreads();
    }
    if (t < SCAN_BLOCKS) bsum[t] = (t == 0) ? 0 : sh[t - 1];
}

__global__ void offsets_kernel(const int* __restrict__ cnt,
                               const int* __restrict__ bsum,
                               int* __restrict__ off,
                               int* __restrict__ cur)
{
    const int t = threadIdx.x;
    const int idx = blockIdx.x * 256 + t;
    const int c = (idx < NN) ? cnt[idx] : 0;
    int x = c;
    #pragma unroll
    for (int d = 1; d < 32; d <<= 1) {
        int y = __shfl_up_sync(0xffffffffu, x, d);
        if ((t & 31) >= d) x += y;
    }
    __shared__ int ws[8];
    if ((t & 31) == 31) ws[t >> 5] = x;
    __syncthreads();
    if (t < 8) {
        int v = ws[t];
        #pragma unroll
        for (int d = 1; d < 8; d <<= 1) {
            int y = __shfl_up_sync(0xffu, v, d);
            if (t >= d) v += y;
        }
        ws[t] = v;
    }
    __syncthreads();
    const int wpre = (t >> 5) ? ws[(t >> 5) - 1] : 0;
    const int excl = x - c + wpre + bsum[blockIdx.x];
    if (idx < NN) {
        off[idx] = excl;
        cur[idx] = excl;
        if (idx == NN - 1) off[NN] = NE;
    }
}

__global__ void scatter_kernel(const int* __restrict__ src,
                               const int* __restrict__ dst,
                               const float* __restrict__ edot,
                               int* __restrict__ cur,
                               int* __restrict__ src_csr,
                               float* __restrict__ edot_csr)
{
    const int e = blockIdx.x * 256 + threadIdx.x;
    if (e >= NE) return;
    const int d = dst[e];
    const int pos = atomicAdd(cur + d, 1);
    src_csr[pos]  = src[e];
    edot_csr[pos] = edot[e];
}

// ---------------------------------------------------------------------------
// Final edge weights, coalesced by original edge id (uses post-layer-1 sdot).
// ---------------------------------------------------------------------------
__global__ void ew_kernel(const int* __restrict__ src,
                          const int* __restrict__ dst,
                          const float* __restrict__ edot,
                          const float2* __restrict__ sdot,
                          float* __restrict__ ew)
{
    const int e = blockIdx.x * 256 + threadIdx.x;
    if (e >= NE) return;
    const float p = sdot[src[e]].x + sdot[dst[e]].y + edot[e];
    ew[e] = 1.f / (1.f + __expf(-p));
}

#define A_STR 73
#define B_STR 136

// ---------------------------------------------------------------------------
// TC embed GEMM (bf16-split): out[rows,H] = X[rows,K] @ W[K,H] + scb*b.
// 512 threads, grid = NCHUNK (one 64-row chunk per block). Warp tile 16x32.
// DEGBIAS: scb = deg[row]. SDOT: writes {o.ws, o.wd} per row.
// ---------------------------------------------------------------------------
template<int K, bool DEGBIAS, bool SDOT>
__global__ void __launch_bounds__(512, 1)
embed_tc_kernel(const float* __restrict__ X,
                const float* __restrict__ W,
                const float* __restrict__ b,
                const float* __restrict__ deg,
                const float* __restrict__ W_top,
                float* __restrict__ out,
                float2* __restrict__ sdot2, int rows)
{
    constexpr int KP = K / 2;
    extern __shared__ uint32_t smu[];
    uint32_t* Ahi = smu;
    uint32_t* Alo = Ahi + KP * A_STR;
    uint32_t* Bhi = Alo + KP * A_STR;
    uint32_t* Blo = Bhi + KP * B_STR;
    float*    prm = (float*)(Blo + KP * B_STR);     // 384 floats: b|ws|wd
    float2*   sdp = (float2*)(prm + 384);           // [64 rows][4 col-partials]

    const int tid  = threadIdx.x;
    const int lane = tid & 31;
    const int w    = tid >> 5;
    const int t4   = lane & 3;
    const int g    = lane >> 2;

    const float2* prm2  = (const float2*)prm;
    float2*       outp2 = (float2*)out;

    // stage W (k-pairs, bf16x2 hi/lo)
    for (int i = tid; i < KP * 128; i += 512) {
        const int kp = i >> 7, n = i & 127;
        const float w0 = W[(size_t)(2 * kp) * 128 + n];
        const float w1 = W[(size_t)(2 * kp + 1) * 128 + n];
        const float h0 = bf16rn(w0);
        const float h1 = bf16rn(w1);
        Bhi[kp * B_STR + n] = bf16pack(h0, h1);
        Blo[kp * B_STR + n] = bf16pack(w0 - h0, w1 - h1);
    }
    for (int i = tid; i < 128; i += 512) {
        prm[i] = b[i];
        if (SDOT) {
            prm[128 + i] = W_top[i];
            prm[256 + i] = W_top[128 + i];
        }
    }

    const int r0 = blockIdx.x * 64;
    const int nrows = min(64, rows - r0);

    // stage x hi/lo (zero-fill tail rows so MMA stays finite)
    for (int i = tid; i < 64 * KP; i += 512) {
        const int r = i / KP, kp = i % KP;
        float2 v = make_float2(0.f, 0.f);
        if (r < nrows)
            v = ((const float2*)X)[(size_t)(r0 + r) * KP + kp];
        const float h0 = bf16rn(v.x);
        const float h1 = bf16rn(v.y);
        Ahi[kp * A_STR + r] = bf16pack(h0, h1);
        Alo[kp * A_STR + r] = bf16pack(v.x - h0, v.y - h1);
    }
    __syncthreads();

    const int roffL = (w >> 2) * 16;
    const int noff  = (w & 3) * 32;
    const int cgrp  = w & 3;

    float c[4][4];
    #pragma unroll
    for (int nt = 0; nt < 4; nt++)
        c[nt][0] = c[nt][1] = c[nt][2] = c[nt][3] = 0.f;

    #pragma unroll 2
    for (int k = 0; k < KP / 8; k++) {
        const int kp0 = 8 * k + t4;
        const uint32_t ah0 = Ahi[kp0 * A_STR + roffL + g];
        const uint32_t ah1 = Ahi[kp0 * A_STR + roffL + g + 8];
        const uint32_t ah2 = Ahi[(kp0 + 4) * A_STR + roffL + g];
        const uint32_t ah3 = Ahi[(kp0 + 4) * A_STR + roffL + g + 8];
        const uint32_t al0 = Alo[kp0 * A_STR + roffL + g];
        const uint32_t al1 = Alo[kp0 * A_STR + roffL + g + 8];
        const uint32_t al2 = Alo[(kp0 + 4) * A_STR + roffL + g];
        const uint32_t al3 = Alo[(kp0 + 4) * A_STR + roffL + g + 8];
        const uint32_t* B0h = Bhi + kp0 * B_STR + noff + g;
        const uint32_t* B1h = Bhi + (kp0 + 4) * B_STR + noff + g;
        const uint32_t* B0l = Blo + kp0 * B_STR + noff + g;
        const uint32_t* B1l = Blo + (kp0 + 4) * B_STR + noff + g;
        #pragma unroll
        for (int nt = 0; nt < 4; nt++) {
            const uint32_t bh0 = B0h[nt * 8];
            const uint32_t bh1 = B1h[nt * 8];
            const uint32_t bl0 = B0l[nt * 8];
            const uint32_t bl1 = B1l[nt * 8];
            mma16816(c[nt], ah0, ah1, ah2, ah3, bh0, bh1);
            mma16816(c[nt], ah0, ah1, ah2, ah3, bl0, bl1);
            mma16816(c[nt], al0, al1, al2, al3, bh0, bh1);
        }
    }

    const int lr0 = roffL + g;
    const int lr1 = roffL + g + 8;
    const int cr0 = min(lr0, nrows - 1);
    const int cr1 = min(lr1, nrows - 1);
    const float scb0 = DEGBIAS ? deg[r0 + cr0] : 1.f;
    const float scb1 = DEGBIAS ? deg[r0 + cr1] : 1.f;
    const int colh0 = cgrp * 16 + t4;

    float d0s = 0.f, d0d = 0.f, d1s = 0.f, d1d = 0.f;
    #pragma unroll
    for (int nt = 0; nt < 4; nt++) {
        const int ch = colh0 + nt * 4;
        const float2 bia = prm2[ch];
        float2 o0, o1;
        o0.x = c[nt][0] + scb0 * bia.x;
        o0.y = c[nt][1] + scb0 * bia.y;
        o1.x = c[nt][2] + scb1 * bia.x;
        o1.y = c[nt][3] + scb1 * bia.y;
        if (lr0 < nrows) outp2[((size_t)r0 + lr0) * 64 + ch] = o0;
        if (lr1 < nrows) outp2[((size_t)r0 + lr1) * 64 + ch] = o1;
        if (SDOT) {
            const float2 ws2 = prm2[64 + ch];
            const float2 wd2 = prm2[128 + ch];
            d0s += o0.x * ws2.x + o0.y * ws2.y;
            d0d += o0.x * wd2.x + o0.y * wd2.y;
            d1s += o1.x * ws2.x + o1.y * ws2.y;
            d1d += o1.x * wd2.x + o1.y * wd2.y;
        }
    }
    if (SDOT) {
        #pragma unroll
        for (int off_ = 1; off_ <= 2; off_ <<= 1) {
            d0s += __shfl_xor_sync(0xffffffffu, d0s, off_);
            d0d += __shfl_xor_sync(0xffffffffu, d0d, off_);
            d1s += __shfl_xor_sync(0xffffffffu, d1s, off_);
            d1d += __shfl_xor_sync(0xffffffffu, d1d, off_);
        }
        if (t4 == 0) {
            sdp[lr0 * 4 + cgrp] = make_float2(d0s, d0d);
            sdp[lr1 * 4 + cgrp] = make_float2(d1s, d1d);
        }
        __syncthreads();
        if (tid < 64 && tid < nrows) {
            float sx = 0.f, sy = 0.f;
            #pragma unroll
            for (int p = 0; p < 4; p++) {
                const float2 a = sdp[tid * 4 + p];
                sx += a.x;
                sy += a.y;
            }
            sdot2[r0 + tid] = make_float2(sx, sy);
        }
    }
}

// ---------------------------------------------------------------------------
// Fused GNN layer (R11-proven 512-thread core) + dynamic chunk scheduling.
// ---------------------------------------------------------------------------
#define A_PLANE (128 * A_STR)
#define B_PLANE (128 * B_STR)
#define SMEM_TC ((2 * A_PLANE + 2 * B_PLANE + 640 + 1024 + 1024 + 4) * 4)

template<bool LAST>
__global__ void __launch_bounds__(512, 1)
gnn_fused_kernel(const float* __restrict__ nh_old,
                 float* __restrict__ nh_new,
                 const float* __restrict__ agg_base,
                 const int* __restrict__ off,
                 const int* __restrict__ src_csr,
                 const float* __restrict__ edot_csr,
                 const float2* __restrict__ sdot_cur,
                 float2* __restrict__ sdot_nxt,
                 const float* __restrict__ W,      // [256,128]
                 const float* __restrict__ b,
                 const float* __restrict__ lns,
                 const float* __restrict__ lnb,
                 const float* __restrict__ W_top,
                 int* __restrict__ ctr, int rows)
{
    extern __shared__ uint32_t smu[];
    uint32_t* Ahi = smu;
    uint32_t* Alo = Ahi + A_PLANE;
    uint32_t* Bhi = Alo + A_PLANE;
    uint32_t* Blo = Bhi + B_PLANE;
    float*    prm = (float*)(Blo + B_PLANE);        // 640 floats: b|lns|lnb|ws|wd
    float2*   red = (float2*)(prm + 640);           // [64 rows][4 col-partials]
    float2*   sdp = red + 256;                      // [64 rows][4 col-partials]
    int*      s_chunk = (int*)(sdp + 256);

    const int tid  = threadIdx.x;
    const int lane = tid & 31;
    const int w    = tid >> 5;
    const int t4   = lane & 3;
    const int g    = lane >> 2;

    const float2* nh2   = (const float2*)nh_old;
    float2*       outp2 = (float2*)nh_new;
    const float2* prm2  = (const float2*)prm;

    // ---- stage W (once): packed bf16x2 hi/lo planes ----
    for (int i = tid; i < 128 * 128; i += 512) {
        const int kp = i >> 7, n = i & 127;
        const float w0 = W[(size_t)(2 * kp) * 128 + n];
        const float w1 = W[(size_t)(2 * kp + 1) * 128 + n];
        const float h0 = bf16rn(w0);
        const float h1 = bf16rn(w1);
        Bhi[kp * B_STR + n] = bf16pack(h0, h1);
        Blo[kp * B_STR + n] = bf16pack(w0 - h0, w1 - h1);
    }
    for (int i = tid; i < 128; i += 512) {
        prm[i]       = b[i];
        prm[128 + i] = lns[i];
        prm[256 + i] = lnb[i];
        prm[384 + i] = W_top[i];
        prm[512 + i] = W_top[128 + i];
    }

    const int roffL = (w >> 2) * 16;     // row group: 0/16/32/48
    const int noff  = (w & 3) * 32;      // col group: 0/32/64/96
    const int cgrp  = w & 3;

    for (;;) {
        __syncthreads();   // protect prior chunk's smem + W staging on first iter
        if (tid == 0) *s_chunk = atomicAdd(ctr, 1);
        __syncthreads();
        const int chunk = *s_chunk;
        if (chunk >= NCHUNK) break;
        const int r0 = chunk * 64;
        const int nrows = min(64, rows - r0);

        // ---- stage + aggregate: warp owns nodes w*4 .. w*4+3 ----
        for (int q = 0; q < 4; q++) {
            const int rl = w * 4 + q;
            float4 nh4 = make_float4(0.f, 0.f, 0.f, 0.f);
            float4 acc = make_float4(0.f, 0.f, 0.f, 0.f);
            if (rl < nrows) {
                const int node = r0 + rl;
                nh4 = ((const float4*)nh_old)[(size_t)node * HV4 + lane];
                acc = ((const float4*)agg_base)[(size_t)node * HV4 + lane];
                const float sdy = sdot_cur[node].y;
                const int beg = off[node], end = off[node + 1];
                for (int jb = beg; jb < end; jb += 32) {
                    const int j = jb + lane;
                    float wgt = 0.f;
                    int   sj  = 0;
                    if (j < end) {
                        sj = src_csr[j];
                        const float p = sdot_cur[sj].x + sdy + edot_csr[j];
                        wgt = 1.f / (1.f + __expf(-p));
                    }
                    const int m = min(32, end - jb);
                    float4 a1 = make_float4(0.f, 0.f, 0.f, 0.f);
                    float4 a2 = a1, a3 = a1;
                    int jj = 0;
                    for (; jj + 4 <= m; jj += 4) {
                        const int s0 = __shfl_sync(0xffffffffu, sj, jj);
                        const int s1 = __shfl_sync(0xffffffffu, sj, jj + 1);
                        const int s2 = __shfl_sync(0xffffffffu, sj, jj + 2);
                        const int s3 = __shfl_sync(0xffffffffu, sj, jj + 3);
                        const float w0 = __shfl_sync(0xffffffffu, wgt, jj);
                        const float w1 = __shfl_sync(0xffffffffu, wgt, jj + 1);
                        const float w2 = __shfl_sync(0xffffffffu, wgt, jj + 2);
                        const float w3 = __shfl_sync(0xffffffffu, wgt, jj + 3);
                        const float4 f0 = ((const float4*)nh_old)[(size_t)s0 * HV4 + lane];
                        const float4 f1 = ((const float4*)nh_old)[(size_t)s1 * HV4 + lane];
                        const float4 f2 = ((const float4*)nh_old)[(size_t)s2 * HV4 + lane];
                        const float4 f3 = ((const float4*)nh_old)[(size_t)s3 * HV4 + lane];
                        fma4(acc, f0, w0);
                        fma4(a1, f1, w1);
                        fma4(a2, f2, w2);
                        fma4(a3, f3, w3);
                    }
                    for (; jj < m; jj++) {
                        const int s0 = __shfl_sync(0xffffffffu, sj, jj);
                        const float w0 = __shfl_sync(0xffffffffu, wgt, jj);
                        const float4 f0 = ((const float4*)nh_old)[(size_t)s0 * HV4 + lane];
                        fma4(acc, f0, w0);
                    }
                    acc.x += a1.x + a2.x + a3.x;
                    acc.y += a1.y + a2.y + a3.y;
                    acc.z += a1.z + a2.z + a3.z;
                    acc.w += a1.w + a2.w + a3.w;
                }
            }
            const float hx = bf16rn(nh4.x), hy = bf16rn(nh4.y);
            const float hz = bf16rn(nh4.z), hw = bf16rn(nh4.w);
            Ahi[(2 * lane) * A_STR + rl]     = bf16pack(hx, hy);
            Ahi[(2 * lane + 1) * A_STR + rl] = bf16pack(hz, hw);
            Alo[(2 * lane) * A_STR + rl]     = bf16pack(nh4.x - hx, nh4.y - hy);
            Alo[(2 * lane + 1) * A_STR + rl] = bf16pack(nh4.z - hz, nh4.w - hw);
            const float ax = bf16rn(acc.x), ay = bf16rn(acc.y);
            const float az = bf16rn(acc.z), aw = bf16rn(acc.w);
            Ahi[(64 + 2 * lane) * A_STR + rl] = bf16pack(ax, ay);
            Ahi[(65 + 2 * lane) * A_STR + rl] = bf16pack(az, aw);
            Alo[(64 + 2 * lane) * A_STR + rl] = bf16pack(acc.x - ax, acc.y - ay);
            Alo[(65 + 2 * lane) * A_STR + rl] = bf16pack(acc.z - az, acc.w - aw);
        }
        __syncthreads();

        // ---- MMA mainloop: C[4 n-tiles][4] ----
        float c[4][4];
        #pragma unroll
        for (int nt = 0; nt < 4; nt++)
            c[nt][0] = c[nt][1] = c[nt][2] = c[nt][3] = 0.f;

        #pragma unroll 2
        for (int k = 0; k < 16; k++) {
            const int kp0 = 8 * k + t4;
            const uint32_t ah0 = Ahi[kp0 * A_STR + roffL + g];
            const uint32_t ah1 = Ahi[kp0 * A_STR + roffL + g + 8];
            const uint32_t ah2 = Ahi[(kp0 + 4) * A_STR + roffL + g];
            const uint32_t ah3 = Ahi[(kp0 + 4) * A_STR + roffL + g + 8];
            const uint32_t al0 = Alo[kp0 * A_STR + roffL + g];
            const uint32_t al1 = Alo[kp0 * A_STR + roffL + g + 8];
            const uint32_t al2 = Alo[(kp0 + 4) * A_STR + roffL + g];
            const uint32_t al3 = Alo[(kp0 + 4) * A_STR + roffL + g + 8];
            const uint32_t* B0h = Bhi + kp0 * B_STR + noff + g;
            const uint32_t* B1h = Bhi + (kp0 + 4) * B_STR + noff + g;
            const uint32_t* B0l = Blo + kp0 * B_STR + noff + g;
            const uint32_t* B1l = Blo + (kp0 + 4) * B_STR + noff + g;
            #pragma unroll
            for (int nt = 0; nt < 4; nt++) {
                const uint32_t bh0 = B0h[nt * 8];
                const uint32_t bh1 = B1h[nt * 8];
                const uint32_t bl0 = B0l[nt * 8];
                const uint32_t bl1 = B1l[nt * 8];
                mma16816(c[nt], ah0, ah1, ah2, ah3, bh0, bh1);
                mma16816(c[nt], ah0, ah1, ah2, ah3, bl0, bl1);
                mma16816(c[nt], al0, al1, al2, al3, bh0, bh1);
            }
        }

        // ---- epilogue ----
        const int lr0 = roffL + g;
        const int lr1 = roffL + g + 8;
        const size_t gr0 = (size_t)r0 + min(lr0, nrows - 1);
        const size_t gr1 = (size_t)r0 + min(lr1, nrows - 1);
        const int colh0 = cgrp * 16 + t4;

        float2 v0[4], v1[4];
        float s0 = 0.f, ss0 = 0.f, s1r = 0.f, ss1r = 0.f;
        #pragma unroll
        for (int nt = 0; nt < 4; nt++) {
            const int ch = colh0 + nt * 4;
            const float2 res0 = nh2[gr0 * 64 + ch];
            const float2 res1 = nh2[gr1 * 64 + ch];
            const float2 bia  = prm2[ch];
            float2 a0v, a1v;
            a0v.x = c[nt][0] + res0.x + bia.x;
            a0v.y = c[nt][1] + res0.y + bia.y;
            a1v.x = c[nt][2] + res1.x + bia.x;
            a1v.y = c[nt][3] + res1.y + bia.y;
            v0[nt] = a0v;
            v1[nt] = a1v;
            s0  += a0v.x + a0v.y;  ss0  += a0v.x * a0v.x + a0v.y * a0v.y;
            s1r += a1v.x + a1v.y;  ss1r += a1v.x * a1v.x + a1v.y * a1v.y;
        }
        #pragma unroll
        for (int off_ = 1; off_ <= 2; off_ <<= 1) {
            s0   += __shfl_xor_sync(0xffffffffu, s0, off_);
            ss0  += __shfl_xor_sync(0xffffffffu, ss0, off_);
            s1r  += __shfl_xor_sync(0xffffffffu, s1r, off_);
            ss1r += __shfl_xor_sync(0xffffffffu, ss1r, off_);
        }
        if (t4 == 0) {
            red[lr0 * 4 + cgrp] = make_float2(s0, ss0);
            red[lr1 * 4 + cgrp] = make_float2(s1r, ss1r);
        }
        __syncthreads();

        float sum0 = 0.f, sq0 = 0.f, sum1 = 0.f, sq1 = 0.f;
        #pragma unroll
        for (int p = 0; p < 4; p++) {
            const float2 a = red[lr0 * 4 + p];
            const float2 bb = red[lr1 * 4 + p];
            sum0 += a.x;  sq0 += a.y;
            sum1 += bb.x; sq1 += bb.y;
        }
        const float mean0 = sum0 * (1.f / 128.f);
        const float var0  = sq0 * (1.f / 128.f) - mean0 * mean0;
        const float rstd0 = rsqrtf(var0 + 1e-6f);
        const float mean1 = sum1 * (1.f / 128.f);
        const float var1  = sq1 * (1.f / 128.f) - mean1 * mean1;
        const float rstd1 = rsqrtf(var1 + 1e-6f);

        float d0s = 0.f, d0d = 0.f, d1s = 0.f, d1d = 0.f;
        #pragma unroll
        for (int nt = 0; nt < 4; nt++) {
            const int ch = colh0 + nt * 4;
            const float2 sc2 = prm2[64 + ch];
            const float2 bi2 = prm2[128 + ch];
            float2 o0, o1;
            o0.x = fmaxf((v0[nt].x - mean0) * rstd0 * sc2.x + bi2.x, 0.f);
            o0.y = fmaxf((v0[nt].y - mean0) * rstd0 * sc2.y + bi2.y, 0.f);
            o1.x = fmaxf((v1[nt].x - mean1) * rstd1 * sc2.x + bi2.x, 0.f);
            o1.y = fmaxf((v1[nt].y - mean1) * rstd1 * sc2.y + bi2.y, 0.f);
            if (lr0 < nrows) outp2[((size_t)r0 + lr0) * 64 + ch] = o0;
            if (lr1 < nrows) outp2[((size_t)r0 + lr1) * 64 + ch] = o1;
            if (!LAST) {
                const float2 ws2 = prm2[192 + ch];
                const float2 wd2 = prm2[256 + ch];
                d0s += o0.x * ws2.x + o0.y * ws2.y;
                d0d += o0.x * wd2.x + o0.y * wd2.y;
                d1s += o1.x * ws2.x + o1.y * ws2.y;
                d1d += o1.x * wd2.x + o1.y * wd2.y;
            }
        }
        if (!LAST) {
            #pragma unroll
            for (int off_ = 1; off_ <= 2; off_ <<= 1) {
                d0s += __shfl_xor_sync(0xffffffffu, d0s, off_);
                d0d += __shfl_xor_sync(0xffffffffu, d0d, off_);
                d1s += __shfl_xor_sync(0xffffffffu, d1s, off_);
                d1d += __shfl_xor_sync(0xffffffffu, d1d, off_);
            }
            if (t4 == 0) {
                sdp[lr0 * 4 + cgrp] = make_float2(d0s, d0d);
                sdp[lr1 * 4 + cgrp] = make_float2(d1s, d1d);
            }
            __syncthreads();
            if (tid < 64 && tid < nrows) {
                float sx = 0.f, sy = 0.f;
                #pragma unroll
                for (int p = 0; p < 4; p++) {
                    const float2 a = sdp[tid * 4 + p];
                    sx += a.x;
                    sy += a.y;
                }
                sdot_nxt[r0 + tid] = make_float2(sx, sy);
            }
        }
    }
}

extern "C" void kernel_launch(void* const* d_in, const int* in_sizes, int n_in,
                              void* d_out, int out_size)
{
    const float* node_features = (const float*)d_in[0];
    const float* edge_features = (const float*)d_in[1];
    const int*   edge_indices  = (const int*)d_in[2];
    const float* W_node   = (const float*)d_in[3];
    const float* b_node   = (const float*)d_in[4];
    const float* W_edge   = (const float*)d_in[5];
    const float* b_edge   = (const float*)d_in[6];
    const float* W_gnn    = (const float*)d_in[7];
    const float* b_gnn    = (const float*)d_in[8];
    const float* W_top    = (const float*)d_in[9];
    const float* b_top    = (const float*)d_in[10];
    const float* ln_scale = (const float*)d_in[11];
    const float* ln_bias  = (const float*)d_in[12];

    float *nh_a, *nh_b, *agg_base, *escratch, *edot, *wcombo;
    int *cnt, *offp, *cur, *src_csr, *bsum, *ctr;
    float *edot_csr;
    cudaGetSymbolAddress((void**)&nh_a,     g_node_h);
    cudaGetSymbolAddress((void**)&nh_b,     g_node_h2);
    cudaGetSymbolAddress((void**)&agg_base, g_agg_base);
    cudaGetSymbolAddress((void**)&escratch, g_escratch);
    cudaGetSymbolAddress((void**)&edot,     g_edot);
    cudaGetSymbolAddress((void**)&wcombo,   g_wcombo);
    cudaGetSymbolAddress((void**)&cnt,      g_cnt);
    cudaGetSymbolAddress((void**)&offp,     g_off);
    cudaGetSymbolAddress((void**)&cur,      g_cur);
    cudaGetSymbolAddress((void**)&src_csr,  g_src_csr);
    cudaGetSymbolAddress((void**)&bsum,     g_bsum);
    cudaGetSymbolAddress((void**)&ctr,      g_ctr);
    cudaGetSymbolAddress((void**)&edot_csr, g_edot_csr);

    float* eaggF  = escratch;              // [NN,64] precompute phase
    float* deg    = escratch + NN * 64;    // [NN]
    float2* sdot_a = (float2*)escratch;            // [NN] layer phase
    float2* sdot_b = (float2*)(escratch + 2 * NN); // [NN]

    float* out_node = (float*)d_out;
    float* out_ew   = (float*)d_out + (size_t)NN * H;

    const int* srcp = edge_indices;
    const int* dstp = edge_indices + NE;

    const int smem_te128 = (2 * 64 * A_STR + 2 * 64 * B_STR + 384 + 1024) * 4;
    const int smem_te64  = (2 * 32 * A_STR + 2 * 32 * B_STR + 384 + 1024) * 4;
    cudaFuncSetAttribute((const void*)embed_tc_kernel<128, false, true>,
                         cudaFuncAttributeMaxDynamicSharedMemorySize, smem_te128);
    cudaFuncSetAttribute((const void*)embed_tc_kernel<64, true, false>,
                         cudaFuncAttributeMaxDynamicSharedMemorySize, smem_te64);
    cudaFuncSetAttribute((const void*)gnn_fused_kernel<false>,
                         cudaFuncAttributeMaxDynamicSharedMemorySize, SMEM_TC);
    cudaFuncSetAttribute((const void*)gnn_fused_kernel<true>,
                         cudaFuncAttributeMaxDynamicSharedMemorySize, SMEM_TC);

    // --- one-time precompute + CSR build ---
    combo_kernel<<<1, 64>>>(W_edge, W_top, b_edge, b_top, wcombo, ctr);
    zero_kernel<<<(NN * 65 / 4 + 255) / 256, 256>>>((float4*)escratch, NN * 65 / 4);
    zero_kernel<<<(NN / 4 + 255) / 256, 256>>>((float4*)cnt, NN / 4);
    edge_pre_kernel<<<NE / 8, 256>>>(edge_features, dstp, wcombo, eaggF, deg, cnt, edot);
    sum_kernel<<<SCAN_BLOCKS, 256>>>(cnt, bsum);
    scanb_kernel<<<1, 256>>>(bsum);
    offsets_kernel<<<SCAN_BLOCKS, 256>>>(cnt, bsum, offp, cur);
    scatter_kernel<<<(NE + 255) / 256, 256>>>(srcp, dstp, edot, cur, src_csr, edot_csr);
    embed_tc_kernel<64, true, false><<<NCHUNK, 512, smem_te64>>>(
        eaggF, W_edge, b_edge, deg, nullptr, agg_base, nullptr, NN);
    embed_tc_kernel<128, false, true><<<NCHUNK, 512, smem_te128>>>(
        node_features, W_node, b_node, nullptr, W_top, nh_a, sdot_a, NN);

    // --- layers (fused), ping-pong buffers, dynamic scheduling ---
    gnn_fused_kernel<false><<<148, 512, SMEM_TC>>>(
        nh_a, nh_b, agg_base, offp, src_csr, edot_csr,
        sdot_a, sdot_b,
        W_gnn + (size_t)0 * 256 * H, b_gnn + 0 * H, ln_scale + 0 * H, ln_bias + 0 * H,
        W_top, ctr + 0, NN);
    gnn_fused_kernel<false><<<148, 512, SMEM_TC>>>(
        nh_b, nh_a, agg_base, offp, src_csr, edot_csr,
        sdot_b, sdot_a,
        W_gnn + (size_t)1 * 256 * H, b_gnn + 1 * H, ln_scale + 1 * H, ln_bias + 1 * H,
        W_top, ctr + 1, NN);
    ew_kernel<<<(NE + 255) / 256, 256>>>(srcp, dstp, edot, sdot_a, out_ew);
    gnn_fused_kernel<true><<<148, 512, SMEM_TC>>>(
        nh_a, out_node, agg_base, offp, src_csr, edot_csr,
        sdot_a, nullptr,
        W_gnn + (size_t)2 * 256 * H, b_gnn + 2 * H, ln_scale + 2 * H, ln_bias + 2 * H,
        W_top, ctr + 2, NN);
}